// round 4
// baseline (speedup 1.0000x reference)
#include <cuda_runtime.h>

// Problem constants (all powers of two)
#define NN   2
#define CC   16
#define DHW  (32 * 128 * 128)       // 524288 = 2^19
#define MV   (NN * DHW)             // 1048576 voxels = 2^20
#define LOG2_DHW 19

#define THREADS 256
#define GRID    ((MV / 4) / THREADS)   // 1024 blocks

// Per-block partials: written unconditionally every launch -> no init needed.
__device__ float        g_psum[GRID];
__device__ int          g_pcnt[GRID];
// Self-resetting ticket: atomicInc(&t, GRID-1) wraps to 0 after exactly GRID
// increments, so every launch starts from 0. Deterministic across replays.
__device__ unsigned int g_ticket = 0;

__global__ __launch_bounds__(THREADS) void ord_fused_kernel(
    const float* __restrict__ pred,
    const int*   __restrict__ target,
    const int*   __restrict__ mask,
    float*       __restrict__ out)
{
    const int g  = blockIdx.x * THREADS + threadIdx.x;     // 4-voxel group id
    const int v4 = g << 2;                                 // first voxel in group
    const int n  = v4 >> LOG2_DHW;                         // batch index
    const int v  = v4 & (DHW - 1);                         // index within DHW

    const size_t nbase = (size_t)n * CC * DHW;             // start of batch n in pred/target

    const int4 m4 = *reinterpret_cast<const int4*>(mask + (size_t)n * DHW + v);
    const int4 t4 = *reinterpret_cast<const int4*>(target + nbase + v); // channel 0 (broadcast)

    const bool va = m4.x > 0;
    const bool vb = m4.y > 0;
    const bool vc = m4.z > 0;
    const bool vd = m4.w > 0;

    int cnt = (int)va + (int)vb + (int)vc + (int)vd;

    const float* pbase = pred + nbase + v;

    float s = 0.0f;
    #pragma unroll
    for (int c = 0; c < CC; c++) {
        const float4 p = *reinterpret_cast<const float4*>(pbase + (size_t)c * DHW);

        float xa = (c <= t4.x) ? p.x : 1.0f - p.x;
        float xb = (c <= t4.y) ? p.y : 1.0f - p.y;
        float xc = (c <= t4.z) ? p.z : 1.0f - p.z;
        float xd = (c <= t4.w) ? p.w : 1.0f - p.w;

        xa = fminf(fmaxf(xa, 1e-8f), 1e8f);
        xb = fminf(fmaxf(xb, 1e-8f), 1e8f);
        xc = fminf(fmaxf(xc, 1e-8f), 1e8f);
        xd = fminf(fmaxf(xd, 1e-8f), 1e8f);

        // accumulate log2; multiply by ln(2) once at the very end
        s += va ? __log2f(xa) : 0.0f;
        s += vb ? __log2f(xb) : 0.0f;
        s += vc ? __log2f(xc) : 0.0f;
        s += vd ? __log2f(xd) : 0.0f;
    }

    // warp reduction
    #pragma unroll
    for (int off = 16; off > 0; off >>= 1) {
        s   += __shfl_xor_sync(0xffffffffu, s, off);
        cnt += __shfl_xor_sync(0xffffffffu, cnt, off);
    }

    __shared__ float sh_s[8];
    __shared__ int   sh_c[8];
    __shared__ int   sh_last;
    const int wid = threadIdx.x >> 5;
    const int lid = threadIdx.x & 31;
    if (lid == 0) { sh_s[wid] = s; sh_c[wid] = cnt; }
    __syncthreads();

    if (threadIdx.x == 0) {
        float bs = 0.0f;
        int   bc = 0;
        #pragma unroll
        for (int i = 0; i < 8; i++) { bs += sh_s[i]; bc += sh_c[i]; }
        g_psum[blockIdx.x] = bs;
        g_pcnt[blockIdx.x] = bc;
        __threadfence();                               // partials visible before ticket
        unsigned int old = atomicInc(&g_ticket, GRID - 1u);
        sh_last = (old == GRID - 1u);                  // wraps to 0 for next launch
    }
    __syncthreads();

    if (sh_last) {
        __threadfence();                               // acquire: see all partials
        // 1024 partials, 256 threads -> 4 each
        double ds = 0.0;
        int    dc = 0;
        #pragma unroll
        for (int i = 0; i < GRID / THREADS; i++) {
            const int idx = threadIdx.x + i * THREADS;
            ds += (double)g_psum[idx];
            dc += g_pcnt[idx];
        }
        // warp reduce doubles
        #pragma unroll
        for (int off = 16; off > 0; off >>= 1) {
            ds += __shfl_xor_sync(0xffffffffu, ds, off);
            dc += __shfl_xor_sync(0xffffffffu, dc, off);
        }
        __shared__ double sh_ds[8];
        __shared__ int    sh_dc[8];
        if (lid == 0) { sh_ds[wid] = ds; sh_dc[wid] = dc; }
        __syncthreads();
        if (threadIdx.x == 0) {
            double fs = 0.0;
            int    fc = 0;
            #pragma unroll
            for (int i = 0; i < 8; i++) { fs += sh_ds[i]; fc += sh_dc[i]; }
            const double LN2 = 0.69314718055994530942;
            out[0] = (float)((fs * LN2) / (-(double)fc));
        }
    }
}

extern "C" void kernel_launch(void* const* d_in, const int* in_sizes, int n_in,
                              void* d_out, int out_size)
{
    const float* pred   = (const float*)d_in[0];
    const int*   target = (const int*)d_in[1];
    const int*   mask   = (const int*)d_in[2];
    float*       out    = (float*)d_out;

    ord_fused_kernel<<<GRID, THREADS>>>(pred, target, mask, out);
}

// round 5
// speedup vs baseline: 1.7143x; 1.7143x over previous
#include <cuda_runtime.h>

// Problem constants (all powers of two)
#define NN   2
#define CC   16
#define DHW  (32 * 128 * 128)       // 524288 = 2^19
#define MV   (NN * DHW)             // 1048576 voxels = 2^20
#define LOG2_DHW 19

#define THREADS 256
#define GRID    ((MV / 4) / THREADS)   // 1024 blocks

// Per-block partials: written unconditionally by every block on every launch,
// and consumed by the (stream-ordered) final kernel. No init kernel needed.
__device__ float g_psum[GRID];
__device__ int   g_pcnt[GRID];

// Process one batch of NB channels starting at c0. Loads are front-batched so
// ptxas can issue them all before any dependent compute (high MLP).
template <int C0, int NB>
__device__ __forceinline__ void channel_batch(
    const float* __restrict__ pbase, const int4 t4,
    float& sa, float& sb, float& sc, float& sd)
{
    float4 p[NB];
    #pragma unroll
    for (int i = 0; i < NB; i++)
        p[i] = *reinterpret_cast<const float4*>(pbase + (size_t)(C0 + i) * DHW);

    #pragma unroll
    for (int i = 0; i < NB; i++) {
        const int c = C0 + i;
        float xa = (c <= t4.x) ? p[i].x : 1.0f - p[i].x;
        float xb = (c <= t4.y) ? p[i].y : 1.0f - p[i].y;
        float xc = (c <= t4.z) ? p[i].z : 1.0f - p[i].z;
        float xd = (c <= t4.w) ? p[i].w : 1.0f - p[i].w;

        // pred in [0,1) -> x in [0,1]; clamp low end only matters, result finite
        xa = fminf(fmaxf(xa, 1e-8f), 1e8f);
        xb = fminf(fmaxf(xb, 1e-8f), 1e8f);
        xc = fminf(fmaxf(xc, 1e-8f), 1e8f);
        xd = fminf(fmaxf(xd, 1e-8f), 1e8f);

        sa += __log2f(xa);
        sb += __log2f(xb);
        sc += __log2f(xc);
        sd += __log2f(xd);
    }
}

__global__ __launch_bounds__(THREADS) void ord_main_kernel(
    const float* __restrict__ pred,
    const int*   __restrict__ target,
    const int*   __restrict__ mask)
{
    const int g  = blockIdx.x * THREADS + threadIdx.x;     // 4-voxel group id
    const int v4 = g << 2;                                 // first voxel in group
    const int n  = v4 >> LOG2_DHW;                         // batch index
    const int v  = v4 & (DHW - 1);                         // index within DHW

    const size_t nbase = (size_t)n * CC * DHW;

    const int4 m4 = *reinterpret_cast<const int4*>(mask + (size_t)n * DHW + v);
    const int4 t4 = *reinterpret_cast<const int4*>(target + nbase + v); // ch 0 (broadcast)

    const float* pbase = pred + nbase + v;

    // Accumulate each voxel-lane unconditionally; fold the mask once at the end.
    float sa = 0.0f, sb = 0.0f, sc = 0.0f, sd = 0.0f;
    channel_batch<0, 8>(pbase, t4, sa, sb, sc, sd);
    channel_batch<8, 8>(pbase, t4, sa, sb, sc, sd);

    const bool va = m4.x > 0;
    const bool vb = m4.y > 0;
    const bool vc = m4.z > 0;
    const bool vd = m4.w > 0;

    float s  = (va ? sa : 0.0f) + (vb ? sb : 0.0f)
             + (vc ? sc : 0.0f) + (vd ? sd : 0.0f);
    int  cnt = (int)va + (int)vb + (int)vc + (int)vd;

    // warp reduction
    #pragma unroll
    for (int off = 16; off > 0; off >>= 1) {
        s   += __shfl_xor_sync(0xffffffffu, s, off);
        cnt += __shfl_xor_sync(0xffffffffu, cnt, off);
    }

    __shared__ float sh_s[8];
    __shared__ int   sh_c[8];
    const int wid = threadIdx.x >> 5;
    const int lid = threadIdx.x & 31;
    if (lid == 0) { sh_s[wid] = s; sh_c[wid] = cnt; }
    __syncthreads();

    if (threadIdx.x == 0) {
        float bs = 0.0f;
        int   bc = 0;
        #pragma unroll
        for (int i = 0; i < 8; i++) { bs += sh_s[i]; bc += sh_c[i]; }
        g_psum[blockIdx.x] = bs;
        g_pcnt[blockIdx.x] = bc;
    }
}

__global__ __launch_bounds__(THREADS) void ord_final_kernel(float* __restrict__ out)
{
    // Reduce 1024 partials with 256 threads (4 each).
    float s = 0.0f;
    int   c = 0;
    #pragma unroll
    for (int i = 0; i < GRID / THREADS; i++) {
        const int idx = threadIdx.x + i * THREADS;
        s += g_psum[idx];
        c += g_pcnt[idx];
    }
    #pragma unroll
    for (int off = 16; off > 0; off >>= 1) {
        s += __shfl_xor_sync(0xffffffffu, s, off);
        c += __shfl_xor_sync(0xffffffffu, c, off);
    }

    __shared__ float sh_s[8];
    __shared__ int   sh_c[8];
    const int wid = threadIdx.x >> 5;
    const int lid = threadIdx.x & 31;
    if (lid == 0) { sh_s[wid] = s; sh_c[wid] = c; }
    __syncthreads();

    if (threadIdx.x == 0) {
        double fs = 0.0;
        int    fc = 0;
        #pragma unroll
        for (int i = 0; i < 8; i++) { fs += (double)sh_s[i]; fc += sh_c[i]; }
        const double LN2 = 0.69314718055994530942;
        out[0] = (float)((fs * LN2) / (-(double)fc));
    }
}

extern "C" void kernel_launch(void* const* d_in, const int* in_sizes, int n_in,
                              void* d_out, int out_size)
{
    const float* pred   = (const float*)d_in[0];
    const int*   target = (const int*)d_in[1];
    const int*   mask   = (const int*)d_in[2];
    float*       out    = (float*)d_out;

    ord_main_kernel<<<GRID, THREADS>>>(pred, target, mask);
    ord_final_kernel<<<1, THREADS>>>(out);
}

// round 6
// speedup vs baseline: 1.7273x; 1.0076x over previous
#include <cuda_runtime.h>

// Problem constants (all powers of two)
#define NN   2
#define CC   16
#define DHW  (32 * 128 * 128)       // 524288 = 2^19
#define MV   (NN * DHW)             // 1048576 voxels = 2^20
#define LOG2_DHW 19

#define THREADS 256
#define GRID    ((MV / 4) / THREADS)   // 1024 blocks

// Per-block partials: written unconditionally by every block each launch.
__device__ float g_psum[GRID];
__device__ int   g_pcnt[GRID];
// Self-resetting ticket: atomicInc(&t, GRID-1) wraps to 0 after exactly GRID
// increments -> identical state at the start of every launch/replay.
__device__ unsigned int g_ticket = 0;

// One batch of NB channels starting at C0. Loads front-batched into a live
// array so ptxas issues all NB LDG.128 before any dependent compute (MLP=NB).
template <int C0, int NB>
__device__ __forceinline__ void channel_batch(
    const float* __restrict__ pbase, const int4 t4,
    float& sa, float& sb, float& sc, float& sd)
{
    float4 p[NB];
    #pragma unroll
    for (int i = 0; i < NB; i++)
        p[i] = *reinterpret_cast<const float4*>(pbase + (size_t)(C0 + i) * DHW);

    #pragma unroll
    for (int i = 0; i < NB; i++) {
        const int c = C0 + i;
        float xa = (c <= t4.x) ? p[i].x : 1.0f - p[i].x;
        float xb = (c <= t4.y) ? p[i].y : 1.0f - p[i].y;
        float xc = (c <= t4.z) ? p[i].z : 1.0f - p[i].z;
        float xd = (c <= t4.w) ? p[i].w : 1.0f - p[i].w;

        xa = fminf(fmaxf(xa, 1e-8f), 1e8f);
        xb = fminf(fmaxf(xb, 1e-8f), 1e8f);
        xc = fminf(fmaxf(xc, 1e-8f), 1e8f);
        xd = fminf(fmaxf(xd, 1e-8f), 1e8f);

        sa += __log2f(xa);
        sb += __log2f(xb);
        sc += __log2f(xc);
        sd += __log2f(xd);
    }
}

__global__ __launch_bounds__(THREADS) void ord_fused_kernel(
    const float* __restrict__ pred,
    const int*   __restrict__ target,
    const int*   __restrict__ mask,
    float*       __restrict__ out)
{
    const int g  = blockIdx.x * THREADS + threadIdx.x;     // 4-voxel group id
    const int v4 = g << 2;
    const int n  = v4 >> LOG2_DHW;
    const int v  = v4 & (DHW - 1);

    const size_t nbase = (size_t)n * CC * DHW;

    const int4 m4 = *reinterpret_cast<const int4*>(mask + (size_t)n * DHW + v);
    const int4 t4 = *reinterpret_cast<const int4*>(target + nbase + v); // ch 0

    const float* pbase = pred + nbase + v;

    // Accumulate per voxel-lane unconditionally; fold mask once at the end.
    float sa = 0.0f, sb = 0.0f, sc = 0.0f, sd = 0.0f;
    channel_batch<0, 8>(pbase, t4, sa, sb, sc, sd);
    channel_batch<8, 8>(pbase, t4, sa, sb, sc, sd);

    const bool va = m4.x > 0;
    const bool vb = m4.y > 0;
    const bool vc = m4.z > 0;
    const bool vd = m4.w > 0;

    float s  = (va ? sa : 0.0f) + (vb ? sb : 0.0f)
             + (vc ? sc : 0.0f) + (vd ? sd : 0.0f);
    int  cnt = (int)va + (int)vb + (int)vc + (int)vd;

    // warp reduction
    #pragma unroll
    for (int off = 16; off > 0; off >>= 1) {
        s   += __shfl_xor_sync(0xffffffffu, s, off);
        cnt += __shfl_xor_sync(0xffffffffu, cnt, off);
    }

    __shared__ float sh_s[8];
    __shared__ int   sh_c[8];
    __shared__ int   sh_last;
    const int wid = threadIdx.x >> 5;
    const int lid = threadIdx.x & 31;
    if (lid == 0) { sh_s[wid] = s; sh_c[wid] = cnt; }
    __syncthreads();

    if (threadIdx.x == 0) {
        float bs = 0.0f;
        int   bc = 0;
        #pragma unroll
        for (int i = 0; i < 8; i++) { bs += sh_s[i]; bc += sh_c[i]; }
        g_psum[blockIdx.x] = bs;
        g_pcnt[blockIdx.x] = bc;
        __threadfence();                                  // partials before ticket
        unsigned int old = atomicInc(&g_ticket, GRID - 1u);
        sh_last = (old == GRID - 1u);                     // wraps to 0 next launch
    }
    __syncthreads();

    if (sh_last) {
        __threadfence();                                  // see all partials
        // 1024 partials, 256 threads -> 4 each (float only: keeps regs lean)
        float fs = 0.0f;
        int   fc = 0;
        #pragma unroll
        for (int i = 0; i < GRID / THREADS; i++) {
            const int idx = threadIdx.x + i * THREADS;
            fs += g_psum[idx];
            fc += g_pcnt[idx];
        }
        #pragma unroll
        for (int off = 16; off > 0; off >>= 1) {
            fs += __shfl_xor_sync(0xffffffffu, fs, off);
            fc += __shfl_xor_sync(0xffffffffu, fc, off);
        }
        if (lid == 0) { sh_s[wid] = fs; sh_c[wid] = fc; }
        __syncthreads();
        if (threadIdx.x == 0) {
            double ts = 0.0;
            int    tc = 0;
            #pragma unroll
            for (int i = 0; i < 8; i++) { ts += (double)sh_s[i]; tc += sh_c[i]; }
            const double LN2 = 0.69314718055994530942;
            out[0] = (float)((ts * LN2) / (-(double)tc));
        }
    }
}

extern "C" void kernel_launch(void* const* d_in, const int* in_sizes, int n_in,
                              void* d_out, int out_size)
{
    const float* pred   = (const float*)d_in[0];
    const int*   target = (const int*)d_in[1];
    const int*   mask   = (const int*)d_in[2];
    float*       out    = (float*)d_out;

    ord_fused_kernel<<<GRID, THREADS>>>(pred, target, mask, out);
}

// round 7
// speedup vs baseline: 1.9322x; 1.1186x over previous
#include <cuda_runtime.h>

// Problem constants (all powers of two)
#define NN   2
#define CC   16
#define DHW  (32 * 128 * 128)       // 524288 = 2^19
#define MV   (NN * DHW)             // 1048576 voxels = 2^20
#define LOG2_DHW 19

#define THREADS 256
#define GRID    ((MV / 4) / THREADS)   // 1024 blocks

// Per-block partials: written unconditionally by every block each launch.
__device__ float g_psum[GRID];
__device__ int   g_pcnt[GRID];
// Self-resetting ticket: atomicInc(&t, GRID-1) wraps to 0 after exactly GRID
// increments -> identical state at the start of every launch/replay.
__device__ unsigned int g_ticket = 0;

// One batch of NB channels starting at C0. Loads front-batched into a live
// array so ptxas issues all NB LDG.128 before any dependent compute (MLP=NB).
template <int C0, int NB>
__device__ __forceinline__ void channel_batch(
    const float* __restrict__ pbase, const int4 t4,
    float& sa, float& sb, float& sc, float& sd)
{
    float4 p[NB];
    #pragma unroll
    for (int i = 0; i < NB; i++)
        p[i] = *reinterpret_cast<const float4*>(pbase + (size_t)(C0 + i) * DHW);

    #pragma unroll
    for (int i = 0; i < NB; i++) {
        const int c = C0 + i;
        float xa = (c <= t4.x) ? p[i].x : 1.0f - p[i].x;
        float xb = (c <= t4.y) ? p[i].y : 1.0f - p[i].y;
        float xc = (c <= t4.z) ? p[i].z : 1.0f - p[i].z;
        float xd = (c <= t4.w) ? p[i].w : 1.0f - p[i].w;

        xa = fminf(fmaxf(xa, 1e-8f), 1e8f);
        xb = fminf(fmaxf(xb, 1e-8f), 1e8f);
        xc = fminf(fmaxf(xc, 1e-8f), 1e8f);
        xd = fminf(fmaxf(xd, 1e-8f), 1e8f);

        sa += __log2f(xa);
        sb += __log2f(xb);
        sc += __log2f(xc);
        sd += __log2f(xd);
    }
}

// min-4-blocks/SM -> 64-reg hard ceiling: keeps occupancy at 50% despite the
// in-kernel final-reduction tail (which inflated regs to 78 / occ 34% in R6).
__global__ __launch_bounds__(THREADS, 4) void ord_fused_kernel(
    const float* __restrict__ pred,
    const int*   __restrict__ target,
    const int*   __restrict__ mask,
    float*       __restrict__ out)
{
    const int g  = blockIdx.x * THREADS + threadIdx.x;     // 4-voxel group id
    const int v4 = g << 2;
    const int n  = v4 >> LOG2_DHW;
    const int v  = v4 & (DHW - 1);

    const size_t nbase = (size_t)n * CC * DHW;

    const int4 m4 = *reinterpret_cast<const int4*>(mask + (size_t)n * DHW + v);
    const int4 t4 = *reinterpret_cast<const int4*>(target + nbase + v); // ch 0

    const float* pbase = pred + nbase + v;

    // Accumulate per voxel-lane unconditionally; fold mask once at the end.
    float sa = 0.0f, sb = 0.0f, sc = 0.0f, sd = 0.0f;
    channel_batch<0, 8>(pbase, t4, sa, sb, sc, sd);
    channel_batch<8, 8>(pbase, t4, sa, sb, sc, sd);

    const bool va = m4.x > 0;
    const bool vb = m4.y > 0;
    const bool vc = m4.z > 0;
    const bool vd = m4.w > 0;

    float s  = (va ? sa : 0.0f) + (vb ? sb : 0.0f)
             + (vc ? sc : 0.0f) + (vd ? sd : 0.0f);
    int  cnt = (int)va + (int)vb + (int)vc + (int)vd;

    // warp reduction
    #pragma unroll
    for (int off = 16; off > 0; off >>= 1) {
        s   += __shfl_xor_sync(0xffffffffu, s, off);
        cnt += __shfl_xor_sync(0xffffffffu, cnt, off);
    }

    __shared__ float sh_s[8];
    __shared__ int   sh_c[8];
    __shared__ int   sh_last;
    const int wid = threadIdx.x >> 5;
    const int lid = threadIdx.x & 31;
    if (lid == 0) { sh_s[wid] = s; sh_c[wid] = cnt; }
    __syncthreads();

    if (threadIdx.x == 0) {
        float bs = 0.0f;
        int   bc = 0;
        #pragma unroll
        for (int i = 0; i < 8; i++) { bs += sh_s[i]; bc += sh_c[i]; }
        g_psum[blockIdx.x] = bs;
        g_pcnt[blockIdx.x] = bc;
        __threadfence();                                  // partials before ticket
        unsigned int old = atomicInc(&g_ticket, GRID - 1u);
        sh_last = (old == GRID - 1u);                     // wraps to 0 next launch
    }
    __syncthreads();

    if (sh_last) {
        __threadfence();                                  // see all partials
        // 1024 partials, 256 threads -> 4 each (float only: keeps regs lean)
        float fs = 0.0f;
        int   fc = 0;
        #pragma unroll
        for (int i = 0; i < GRID / THREADS; i++) {
            const int idx = threadIdx.x + i * THREADS;
            fs += g_psum[idx];
            fc += g_pcnt[idx];
        }
        #pragma unroll
        for (int off = 16; off > 0; off >>= 1) {
            fs += __shfl_xor_sync(0xffffffffu, fs, off);
            fc += __shfl_xor_sync(0xffffffffu, fc, off);
        }
        if (lid == 0) { sh_s[wid] = fs; sh_c[wid] = fc; }
        __syncthreads();
        if (threadIdx.x == 0) {
            double ts = 0.0;
            int    tc = 0;
            #pragma unroll
            for (int i = 0; i < 8; i++) { ts += (double)sh_s[i]; tc += sh_c[i]; }
            const double LN2 = 0.69314718055994530942;
            out[0] = (float)((ts * LN2) / (-(double)tc));
        }
    }
}

extern "C" void kernel_launch(void* const* d_in, const int* in_sizes, int n_in,
                              void* d_out, int out_size)
{
    const float* pred   = (const float*)d_in[0];
    const int*   target = (const int*)d_in[1];
    const int*   mask   = (const int*)d_in[2];
    float*       out    = (float*)d_out;

    ord_fused_kernel<<<GRID, THREADS>>>(pred, target, mask, out);
}

// round 10
// speedup vs baseline: 1.9655x; 1.0172x over previous
#include <cuda_runtime.h>

// Problem constants (all powers of two)
#define NN   2
#define CC   16
#define DHW  (32 * 128 * 128)       // 524288 = 2^19
#define MV   (NN * DHW)             // 1048576 voxels = 2^20

#define THREADS 128
#define GRID    ((MV / 8) / THREADS)   // 1024 blocks, 8 voxels per thread
#define NWARPS  (THREADS / 32)

// Per-block partials: written unconditionally by every block each launch.
__device__ float g_psum[GRID];
__device__ int   g_pcnt[GRID];
// Self-resetting ticket: atomicInc(&t, GRID-1) wraps to 0 after exactly GRID
// increments -> identical state at the start of every launch/replay.
__device__ unsigned int g_ticket = 0;

// One batch of NB channels starting at C0. Loads front-batched into a live
// array so ptxas issues all NB LDG.128 before any dependent compute (MLP=NB).
template <int C0, int NB>
__device__ __forceinline__ void channel_batch(
    const float* __restrict__ pbase, const int4 t4,
    float& sa, float& sb, float& sc, float& sd)
{
    float4 p[NB];
    #pragma unroll
    for (int i = 0; i < NB; i++)
        p[i] = *reinterpret_cast<const float4*>(pbase + (size_t)(C0 + i) * DHW);

    #pragma unroll
    for (int i = 0; i < NB; i++) {
        const int c = C0 + i;
        float xa = (c <= t4.x) ? p[i].x : 1.0f - p[i].x;
        float xb = (c <= t4.y) ? p[i].y : 1.0f - p[i].y;
        float xc = (c <= t4.z) ? p[i].z : 1.0f - p[i].z;
        float xd = (c <= t4.w) ? p[i].w : 1.0f - p[i].w;

        xa = fminf(fmaxf(xa, 1e-8f), 1e8f);
        xb = fminf(fmaxf(xb, 1e-8f), 1e8f);
        xc = fminf(fmaxf(xc, 1e-8f), 1e8f);
        xd = fminf(fmaxf(xd, 1e-8f), 1e8f);

        sa += __log2f(xa);
        sb += __log2f(xb);
        sc += __log2f(xc);
        sd += __log2f(xd);
    }
}

// Process one 4-voxel quad (voxel offset v) of batch b; returns masked sum + count.
__device__ __forceinline__ void do_quad(
    const float* __restrict__ pred,
    const int*   __restrict__ target,
    const int*   __restrict__ mask,
    int b, int v, float& s, int& cnt)
{
    const size_t nbase = (size_t)b * CC * DHW;

    const int4 m4 = *reinterpret_cast<const int4*>(mask + (size_t)b * DHW + v);
    const int4 t4 = *reinterpret_cast<const int4*>(target + nbase + v); // ch 0

    const float* pbase = pred + nbase + v;

    float sa = 0.0f, sb = 0.0f, sc = 0.0f, sd = 0.0f;
    channel_batch<0, 8>(pbase, t4, sa, sb, sc, sd);
    channel_batch<8, 8>(pbase, t4, sa, sb, sc, sd);

    const bool va = m4.x > 0;
    const bool vb = m4.y > 0;
    const bool vc = m4.z > 0;
    const bool vd = m4.w > 0;

    s   += (va ? sa : 0.0f) + (vb ? sb : 0.0f)
         + (vc ? sc : 0.0f) + (vd ? sd : 0.0f);
    cnt += (int)va + (int)vb + (int)vc + (int)vd;
}

// 128 threads, min 8 blocks/SM -> 64-reg ceiling, 8 CTAs/SM => n_conc = 1184
// > GRID = 1024 => entire kernel runs in ONE wave (R7 ran 1.73 waves).
__global__ __launch_bounds__(THREADS, 8) void ord_fused_kernel(
    const float* __restrict__ pred,
    const int*   __restrict__ target,
    const int*   __restrict__ mask,
    float*       __restrict__ out)
{
    const int g = blockIdx.x * THREADS + threadIdx.x;  // quad id within one batch
    const int v = g << 2;                              // voxel offset in [0, DHW)

    float s  = 0.0f;
    int   cnt = 0;
    do_quad(pred, target, mask, 0, v, s, cnt);         // batch 0, voxel quad v
    do_quad(pred, target, mask, 1, v, s, cnt);         // batch 1, same quad

    // warp reduction
    #pragma unroll
    for (int off = 16; off > 0; off >>= 1) {
        s   += __shfl_xor_sync(0xffffffffu, s, off);
        cnt += __shfl_xor_sync(0xffffffffu, cnt, off);
    }

    __shared__ float sh_s[NWARPS];
    __shared__ int   sh_c[NWARPS];
    __shared__ int   sh_last;
    const int wid = threadIdx.x >> 5;
    const int lid = threadIdx.x & 31;
    if (lid == 0) { sh_s[wid] = s; sh_c[wid] = cnt; }
    __syncthreads();

    if (threadIdx.x == 0) {
        float bs = 0.0f;
        int   bc = 0;
        #pragma unroll
        for (int i = 0; i < NWARPS; i++) { bs += sh_s[i]; bc += sh_c[i]; }
        g_psum[blockIdx.x] = bs;
        g_pcnt[blockIdx.x] = bc;
        __threadfence();                                  // partials before ticket
        unsigned int old = atomicInc(&g_ticket, GRID - 1u);
        sh_last = (old == GRID - 1u);                     // wraps to 0 next launch
    }
    __syncthreads();

    if (sh_last) {
        __threadfence();                                  // see all partials
        // 1024 partials, 128 threads -> 8 each (float only: keeps regs lean)
        float fs = 0.0f;
        int   fc = 0;
        #pragma unroll
        for (int i = 0; i < GRID / THREADS; i++) {
            const int idx = threadIdx.x + i * THREADS;
            fs += g_psum[idx];
            fc += g_pcnt[idx];
        }
        #pragma unroll
        for (int off = 16; off > 0; off >>= 1) {
            fs += __shfl_xor_sync(0xffffffffu, fs, off);
            fc += __shfl_xor_sync(0xffffffffu, fc, off);
        }
        if (lid == 0) { sh_s[wid] = fs; sh_c[wid] = fc; }
        __syncthreads();
        if (threadIdx.x == 0) {
            double ts = 0.0;
            int    tc = 0;
            #pragma unroll
            for (int i = 0; i < NWARPS; i++) { ts += (double)sh_s[i]; tc += sh_c[i]; }
            const double LN2 = 0.69314718055994530942;
            out[0] = (float)((ts * LN2) / (-(double)tc));
        }
    }
}

extern "C" void kernel_launch(void* const* d_in, const int* in_sizes, int n_in,
                              void* d_out, int out_size)
{
    const float* pred   = (const float*)d_in[0];
    const int*   target = (const int*)d_in[1];
    const int*   mask   = (const int*)d_in[2];
    float*       out    = (float*)d_out;

    ord_fused_kernel<<<GRID, THREADS>>>(pred, target, mask, out);
}